// round 10
// baseline (speedup 1.0000x reference)
#include <cuda_runtime.h>
#include <math.h>

// ---------------- problem constants ----------------
#define BW_   512              // total windows
#define NW_   64               // mask batch
#define N_    343              // tokens per window
#define NROWS 344              // smem rows actually stored
#define PSW   344              // ps / bm row stride (mult of 4)
#define DIM_  96
#define HEADS 3
#define HD    32
#define NN_   (N_ * N_)        // 117649
#define ROWS_TOT (BW_ * N_)    // 175616

// smem float offsets for attn (ks stride 36, vs stride 32, qs stride 36, ps 64x344)
#define KS_OFF 0
#define VS_OFF (NROWS * 36)
#define QS_OFF (NROWS * 36 + NROWS * 32)
#define PS_OFF (2 * NROWS * 36 + NROWS * 32)
#define SM_FLOATS (PS_OFF + 64 * PSW)      // 57792 floats = 231168 B

// ---------------- device scratch ----------------
__device__ float g_q [BW_ * HEADS * N_ * HD];
__device__ float g_k [BW_ * HEADS * N_ * HD];
__device__ float g_v [BW_ * HEADS * N_ * HD];
__device__ float g_ao[ROWS_TOT * DIM_];
__device__ float g_bm[(size_t)NW_ * HEADS * N_ * PSW];   // bias+mask, padded rows

// ---------------- kernel 1: combined bias+mask table ----------------
__global__ void bm_kernel(const int* __restrict__ rpi, const float* __restrict__ table,
                          const float* __restrict__ mask) {
    size_t idx = (size_t)blockIdx.x * blockDim.x + threadIdx.x;
    const size_t total = (size_t)NW_ * HEADS * N_ * PSW;
    if (idx >= total) return;
    int j  = (int)(idx % PSW);
    size_t rest = idx / PSW;
    int i  = (int)(rest % N_);
    int wh = (int)(rest / N_);
    int h  = wh % HEADS;
    int w  = wh / HEADS;
    float v = 0.0f;
    if (j < N_)
        v = table[rpi[i * N_ + j] * HEADS + h] + mask[((size_t)w * N_ + i) * N_ + j];
    g_bm[idx] = v;
}

// ---------------- GEMM core (k-major smem, vectorized operand loads) ----------------
__device__ __forceinline__ void gemm_core(const float* __restrict__ xg4,   // 128x96 tile
                                          const float* __restrict__ wg4,   // 96x96 slice
                                          float* xs_t, float* ws_t,
                                          float acc[8][6], int tid) {
    {
        const float4* xg = (const float4*)xg4;
        for (int i = tid; i < 128 * 24; i += 256) {
            int r = i / 24, c4 = i % 24;
            float4 v = xg[r * 24 + c4];
            xs_t[(c4 * 4 + 0) * 132 + r] = v.x;
            xs_t[(c4 * 4 + 1) * 132 + r] = v.y;
            xs_t[(c4 * 4 + 2) * 132 + r] = v.z;
            xs_t[(c4 * 4 + 3) * 132 + r] = v.w;
        }
    }
    {
        const float4* wg = (const float4*)wg4;
        for (int i = tid; i < 96 * 24; i += 256) {
            int r = i / 24, c4 = i % 24;
            float4 v = wg[r * 24 + c4];
            ws_t[(c4 * 4 + 0) * 100 + r] = v.x;
            ws_t[(c4 * 4 + 1) * 100 + r] = v.y;
            ws_t[(c4 * 4 + 2) * 100 + r] = v.z;
            ws_t[(c4 * 4 + 3) * 100 + r] = v.w;
        }
    }
    __syncthreads();

    const int tx = tid & 15, ty = tid >> 4;
#pragma unroll
    for (int i = 0; i < 8; i++)
#pragma unroll
        for (int j = 0; j < 6; j++) acc[i][j] = 0.0f;

#pragma unroll 4
    for (int k = 0; k < 96; k++) {
        float4 a0 = *(const float4*)&xs_t[k * 132 + ty * 8];
        float4 a1 = *(const float4*)&xs_t[k * 132 + ty * 8 + 4];
        float2 b0 = *(const float2*)&ws_t[k * 100 + tx * 6];
        float2 b1 = *(const float2*)&ws_t[k * 100 + tx * 6 + 2];
        float2 b2 = *(const float2*)&ws_t[k * 100 + tx * 6 + 4];
        float a[8] = {a0.x, a0.y, a0.z, a0.w, a1.x, a1.y, a1.z, a1.w};
        float b[6] = {b0.x, b0.y, b1.x, b1.y, b2.x, b2.y};
#pragma unroll
        for (int i = 0; i < 8; i++)
#pragma unroll
            for (int j = 0; j < 6; j++) acc[i][j] = fmaf(a[i], b[j], acc[i][j]);
    }
}

// ---------------- kernel 2: QKV GEMM ----------------
__global__ __launch_bounds__(256, 2) void qkv_gemm(const float* __restrict__ x,
                                                   const float* __restrict__ W,
                                                   const float* __restrict__ bias) {
    extern __shared__ float sm[];
    float* xs_t = sm;
    float* ws_t = sm + 96 * 132;
    const int tid   = threadIdx.x;
    const int which = blockIdx.y;
    const int m0    = blockIdx.x * 128;

    float acc[8][6];
    gemm_core(x + (size_t)m0 * 96, W + (size_t)which * 96 * 96, xs_t, ws_t, acc, tid);

    const int tx = tid & 15, ty = tid >> 4;
    float* base = (which == 0) ? g_q : (which == 1) ? g_k : g_v;
#pragma unroll
    for (int i = 0; i < 8; i++) {
        int m = m0 + ty * 8 + i;
        int bw = m / N_, n = m - bw * N_;
#pragma unroll
        for (int j = 0; j < 6; j++) {
            int c = tx * 6 + j;
            int h = c >> 5, d = c & 31;
            base[(((size_t)bw * HEADS + h) * N_ + n) * HD + d] = acc[i][j] + bias[which * 96 + c];
        }
    }
}

// ---------------- cp.async helpers ----------------
__device__ __forceinline__ void cp_async16(float* smem_dst, const float* gmem_src) {
    unsigned saddr = (unsigned)__cvta_generic_to_shared(smem_dst);
    asm volatile("cp.async.cg.shared.global [%0], [%1], 16;\n" :: "r"(saddr), "l"(gmem_src));
}
__device__ __forceinline__ void cp_async_commit() {
    asm volatile("cp.async.commit_group;\n" ::: "memory");
}
__device__ __forceinline__ void cp_async_wait0() {
    asm volatile("cp.async.wait_group 0;\n" ::: "memory");
}

// prefetch bm rows for tile i0 into warp-owned ps rows (base ty*2). 86 float4/row.
template<int RPW>
__device__ __forceinline__ void prefetch_bm(int i0, float* ps,
                                            const float* __restrict__ bmb,
                                            int ty, int tx) {
#pragma unroll
    for (int rr = 0; rr < RPW; rr++) {
        int i = i0 + ty * RPW + rr;
        if (i > N_ - 1) i = N_ - 1;                 // clamped rows (discarded later)
        const float* src = bmb + (size_t)i * PSW;
        float* dst = ps + (ty * 2 + rr) * PSW;
        cp_async16(dst + tx * 4,        src + tx * 4);
        cp_async16(dst + (tx + 32) * 4, src + (tx + 32) * 4);
        if (tx < 22)
            cp_async16(dst + (tx + 64) * 4, src + (tx + 64) * 4);
    }
    cp_async_commit();
}

// ---------------- attn tile worker (32 warps, RPW rows per warp) ----------------
// ps row ownership is warp-constant: warp ty ALWAYS uses ps rows [ty*2, ty*2+RPW).
template<int RPW>
__device__ __forceinline__ void attn_tile(int i0, float* sm,
                                          float scl, int b, int h, int ty, int tx) {
    float* ks = sm + KS_OFF;
    float* vs = sm + VS_OFF;
    float* qs = sm + QS_OFF;
    float* ps = sm + PS_OFF;

    // ---- Phase A: S = Q K^T ----
    float acc[RPW][11];
#pragma unroll
    for (int rr = 0; rr < RPW; rr++)
#pragma unroll
        for (int t = 0; t < 11; t++) acc[rr][t] = 0.0f;

#pragma unroll
    for (int d0 = 0; d0 < 32; d0 += 4) {
        float qa[RPW][4];
#pragma unroll
        for (int rr = 0; rr < RPW; rr++) {
            int row = i0 + ty * RPW + rr;
            row = (row < NROWS) ? row : 0;          // qs has NROWS rows
            float4 q4 = *(const float4*)&qs[row * 36 + d0];   // broadcast
            qa[rr][0] = q4.x; qa[rr][1] = q4.y; qa[rr][2] = q4.z; qa[rr][3] = q4.w;
        }
#pragma unroll
        for (int t = 0; t < 11; t++) {
            int j = tx + 32 * t;                     // j>=NROWS reads in-bounds junk; masked later
            float4 k4 = *(const float4*)&ks[j * 36 + d0];
#pragma unroll
            for (int rr = 0; rr < RPW; rr++) {
                acc[rr][t] = fmaf(qa[rr][0], k4.x, acc[rr][t]);
                acc[rr][t] = fmaf(qa[rr][1], k4.y, acc[rr][t]);
                acc[rr][t] = fmaf(qa[rr][2], k4.z, acc[rr][t]);
                acc[rr][t] = fmaf(qa[rr][3], k4.w, acc[rr][t]);
            }
        }
    }

    // ---- wait for this tile's bm prefetch, then softmax (warp-local rows) ----
    cp_async_wait0();
    __syncwarp();
#pragma unroll
    for (int rr = 0; rr < RPW; rr++) {
        const float* bmrow = ps + (ty * 2 + rr) * PSW;
        float mx = -1e30f;
#pragma unroll
        for (int t = 0; t < 11; t++) {
            int j = tx + 32 * t;
            float s = (j < N_) ? fmaf(acc[rr][t], scl, bmrow[j]) : -1e30f;
            acc[rr][t] = s;
            mx = fmaxf(mx, s);
        }
#pragma unroll
        for (int o = 16; o; o >>= 1) mx = fmaxf(mx, __shfl_xor_sync(0xffffffffu, mx, o));
        float sum = 0.0f;
#pragma unroll
        for (int t = 0; t < 11; t++) {
            int j = tx + 32 * t;
            float e = (j < N_) ? __expf(acc[rr][t] - mx) : 0.0f;
            acc[rr][t] = e;
            sum += e;
        }
#pragma unroll
        for (int o = 16; o; o >>= 1) sum += __shfl_xor_sync(0xffffffffu, sum, o);
        float inv = 1.0f / sum;
#pragma unroll
        for (int t = 0; t < 11; t++) {
            int j = tx + 32 * t;
            if (j < PSW)
                ps[(ty * 2 + rr) * PSW + j] = acc[rr][t] * inv;   // overwrite bm with p
        }
    }
    __syncwarp();

    // ---- Phase B: O = P V (lane = output dim) ----
    float o[RPW];
#pragma unroll
    for (int rr = 0; rr < RPW; rr++) o[rr] = 0.0f;

#pragma unroll 2
    for (int j0 = 0; j0 < PSW; j0 += 4) {
        float pa[RPW][4];
#pragma unroll
        for (int rr = 0; rr < RPW; rr++) {
            float4 p4 = *(const float4*)&ps[(ty * 2 + rr) * PSW + j0];  // broadcast
            pa[rr][0] = p4.x; pa[rr][1] = p4.y; pa[rr][2] = p4.z; pa[rr][3] = p4.w;
        }
#pragma unroll
        for (int jj = 0; jj < 4; jj++) {
            float vv = vs[(j0 + jj) * 32 + tx];
#pragma unroll
            for (int rr = 0; rr < RPW; rr++)
                o[rr] = fmaf(pa[rr][jj], vv, o[rr]);
        }
    }
#pragma unroll
    for (int rr = 0; rr < RPW; rr++) {
        int i = i0 + ty * RPW + rr;
        if (i < N_)
            g_ao[((size_t)b * N_ + i) * DIM_ + h * HD + tx] = o[rr];
    }
    __syncwarp();
}

// ---------------- kernel 3: attention (1024 threads = 32 warps = 8/SMSP) ----------------
// smem: ks [344][36], vs [344][32], qs [344][36], ps [64][344] = 231168 B
__global__ __launch_bounds__(1024) void attn_kernel(const float* __restrict__ logit_scale) {
    extern __shared__ float sm[];
    float* ks = sm + KS_OFF;
    float* vs = sm + VS_OFF;
    float* qs = sm + QS_OFF;
    float* ps = sm + PS_OFF;

    const int bx = blockIdx.x;
    const int b  = bx / HEADS;
    const int h  = bx - b * HEADS;
    const int w  = b & (NW_ - 1);
    const int tid = threadIdx.x;
    const int ty = tid >> 5, tx = tid & 31;   // ty: 0..31

    const size_t bh = (size_t)b * HEADS + h;
    const float* qg = g_q + bh * N_ * HD;
    const float* kg = g_k + bh * N_ * HD;
    const float* vg = g_v + bh * N_ * HD;

    const float* bmb = g_bm + ((size_t)w * HEADS + h) * N_ * PSW;

    // tile-0 bm prefetch overlaps staging (ps untouched by staging; warp-private rows)
    prefetch_bm<2>(0, ps, bmb, ty, tx);

    // stage rows 0..343 (row 343 zero-filled), fused q/k L2 normalization
    for (int r = ty; r < NROWS; r += 32) {
        float qv = 0.f, kv = 0.f, vv = 0.f;
        if (r < N_) {
            int off = r * HD + tx;
            qv = qg[off]; kv = kg[off]; vv = vg[off];
        }
        float qss = qv * qv, kss = kv * kv;
#pragma unroll
        for (int o = 16; o; o >>= 1) {
            qss += __shfl_xor_sync(0xffffffffu, qss, o);
            kss += __shfl_xor_sync(0xffffffffu, kss, o);
        }
        float qinv = 1.0f / fmaxf(sqrtf(qss), 1e-12f);
        float kinv = 1.0f / fmaxf(sqrtf(kss), 1e-12f);
        qs[r * 36 + tx] = qv * qinv;
        ks[r * 36 + tx] = kv * kinv;
        vs[r * 32 + tx] = vv;
    }
    __syncthreads();

    const float scl = fminf(__expf(logit_scale[h]), 100.0f);

    // pipeline: prefetch(t) ... PhaseA(t) | wait | softmax(t) PhaseB(t) prefetch(t+1)
#pragma unroll 1
    for (int i0 = 0; i0 < 320; i0 += 64) {
        attn_tile<2>(i0, sm, scl, b, h, ty, tx);
        if (i0 + 64 < 320) prefetch_bm<2>(i0 + 64, ps, bmb, ty, tx);
        else               prefetch_bm<1>(320,     ps, bmb, ty, tx);
    }
    attn_tile<1>(320, sm, scl, b, h, ty, tx);   // rows 320..351 (tail)
}

// ---------------- kernel 4: output projection ----------------
__global__ __launch_bounds__(256, 2) void proj_gemm(const float* __restrict__ W,
                                                    const float* __restrict__ bias,
                                                    float* __restrict__ out) {
    extern __shared__ float sm[];
    float* xs_t = sm;
    float* ws_t = sm + 96 * 132;
    const int tid = threadIdx.x;
    const int m0  = blockIdx.x * 128;

    float acc[8][6];
    gemm_core(g_ao + (size_t)m0 * 96, W, xs_t, ws_t, acc, tid);

    const int tx = tid & 15, ty = tid >> 4;
#pragma unroll
    for (int i = 0; i < 8; i++) {
        int m = m0 + ty * 8 + i;
#pragma unroll
        for (int j = 0; j < 6; j++) {
            int c = tx * 6 + j;
            out[(size_t)m * 96 + c] = acc[i][j] + bias[c];
        }
    }
}

// ---------------- launch ----------------
extern "C" void kernel_launch(void* const* d_in, const int* in_sizes, int n_in,
                              void* d_out, int out_size) {
    const float* x     = (const float*)d_in[0];
    const float* mask  = (const float*)d_in[1];
    const float* Wqkv  = (const float*)d_in[2];
    const float* bqkv  = (const float*)d_in[3];
    const float* Wproj = (const float*)d_in[4];
    const float* bproj = (const float*)d_in[5];
    const float* ls    = (const float*)d_in[6];
    const float* table = (const float*)d_in[7];
    const int*   rpi   = (const int*)d_in[8];
    float* out = (float*)d_out;

    const int smG = (96 * 132 + 96 * 100) * 4;   // 89088 B
    const int smA = SM_FLOATS * 4;               // 231168 B
    cudaFuncSetAttribute(qkv_gemm,  cudaFuncAttributeMaxDynamicSharedMemorySize, smG);
    cudaFuncSetAttribute(proj_gemm, cudaFuncAttributeMaxDynamicSharedMemorySize, smG);
    cudaFuncSetAttribute(attn_kernel, cudaFuncAttributeMaxDynamicSharedMemorySize, smA);

    const size_t bm_total = (size_t)NW_ * HEADS * N_ * PSW;
    bm_kernel<<<(unsigned)((bm_total + 255) / 256), 256>>>(rpi, table, mask);
    qkv_gemm<<<dim3(ROWS_TOT / 128, 3), 256, smG>>>(x, Wqkv, bqkv);
    attn_kernel<<<BW_ * HEADS, 1024, smA>>>(ls);
    proj_gemm<<<ROWS_TOT / 128, 256, smG>>>(Wproj, bproj, out);
}

// round 14
// speedup vs baseline: 1.1309x; 1.1309x over previous
#include <cuda_runtime.h>
#include <math.h>

// ---------------- problem constants ----------------
#define BW_   512              // total windows
#define NW_   64               // mask batch
#define N_    343              // tokens per window
#define NROWS 344              // smem rows actually stored
#define PSW   344              // ps / bm row stride (mult of 4)
#define DIM_  96
#define HEADS 3
#define HD    32
#define NN_   (N_ * N_)        // 117649
#define ROWS_TOT (BW_ * N_)    // 175616

// smem float offsets for attn (ks stride 36, vs stride 32, qs stride 36, ps 64x344)
#define KS_OFF 0
#define VS_OFF (NROWS * 36)
#define QS_OFF (NROWS * 36 + NROWS * 32)
#define PS_OFF (2 * NROWS * 36 + NROWS * 32)
#define SM_FLOATS (PS_OFF + 64 * PSW)      // 57792 floats = 231168 B

// ---------------- f32x2 packed helpers (sm_103a) ----------------
__device__ __forceinline__ unsigned long long f2pack(float lo, float hi) {
    unsigned long long r;
    asm("mov.b64 %0, {%1, %2};" : "=l"(r) : "f"(lo), "f"(hi));
    return r;
}
__device__ __forceinline__ void f2unpack(float& lo, float& hi, unsigned long long v) {
    asm("mov.b64 {%0, %1}, %2;" : "=f"(lo), "=f"(hi) : "l"(v));
}
__device__ __forceinline__ void f2fma(unsigned long long& d, unsigned long long a,
                                      unsigned long long b) {
    asm("fma.rn.f32x2 %0, %1, %2, %3;" : "=l"(d) : "l"(a), "l"(b), "l"(d));
}

// ---------------- device scratch ----------------
__device__ float g_q [BW_ * HEADS * N_ * HD];
__device__ float g_k [BW_ * HEADS * N_ * HD];
__device__ float g_v [BW_ * HEADS * N_ * HD];
__device__ float g_ao[ROWS_TOT * DIM_];
__device__ float g_bm[(size_t)NW_ * HEADS * N_ * PSW];   // bias+mask, padded rows

// ---------------- kernel 1: combined bias+mask table ----------------
__global__ void bm_kernel(const int* __restrict__ rpi, const float* __restrict__ table,
                          const float* __restrict__ mask) {
    size_t idx = (size_t)blockIdx.x * blockDim.x + threadIdx.x;
    const size_t total = (size_t)NW_ * HEADS * N_ * PSW;
    if (idx >= total) return;
    int j  = (int)(idx % PSW);
    size_t rest = idx / PSW;
    int i  = (int)(rest % N_);
    int wh = (int)(rest / N_);
    int h  = wh % HEADS;
    int w  = wh / HEADS;
    float v = 0.0f;
    if (j < N_)
        v = table[rpi[i * N_ + j] * HEADS + h] + mask[((size_t)w * N_ + i) * N_ + j];
    g_bm[idx] = v;
}

// ---------------- GEMM core (k-major smem, packed f32x2 inner loop) ----------------
__device__ __forceinline__ void gemm_core(const float* __restrict__ xg4,   // 128x96 tile
                                          const float* __restrict__ wg4,   // 96x96 slice
                                          float* xs_t, float* ws_t,
                                          float acc[8][6], int tid) {
    {
        const float4* xg = (const float4*)xg4;
        for (int i = tid; i < 128 * 24; i += 256) {
            int r = i / 24, c4 = i % 24;
            float4 v = xg[r * 24 + c4];
            xs_t[(c4 * 4 + 0) * 132 + r] = v.x;
            xs_t[(c4 * 4 + 1) * 132 + r] = v.y;
            xs_t[(c4 * 4 + 2) * 132 + r] = v.z;
            xs_t[(c4 * 4 + 3) * 132 + r] = v.w;
        }
    }
    {
        const float4* wg = (const float4*)wg4;
        for (int i = tid; i < 96 * 24; i += 256) {
            int r = i / 24, c4 = i % 24;
            float4 v = wg[r * 24 + c4];
            ws_t[(c4 * 4 + 0) * 100 + r] = v.x;
            ws_t[(c4 * 4 + 1) * 100 + r] = v.y;
            ws_t[(c4 * 4 + 2) * 100 + r] = v.z;
            ws_t[(c4 * 4 + 3) * 100 + r] = v.w;
        }
    }
    __syncthreads();

    const int tx = tid & 15, ty = tid >> 4;
    unsigned long long acc2[4][6];
#pragma unroll
    for (int i = 0; i < 4; i++)
#pragma unroll
        for (int j = 0; j < 6; j++) acc2[i][j] = 0ull;

#pragma unroll 4
    for (int k = 0; k < 96; k++) {
        float4 a0 = *(const float4*)&xs_t[k * 132 + ty * 8];
        float4 a1 = *(const float4*)&xs_t[k * 132 + ty * 8 + 4];
        float2 b0 = *(const float2*)&ws_t[k * 100 + tx * 6];
        float2 b1 = *(const float2*)&ws_t[k * 100 + tx * 6 + 2];
        float2 b2 = *(const float2*)&ws_t[k * 100 + tx * 6 + 4];
        unsigned long long ap[4];
        ap[0] = f2pack(a0.x, a0.y); ap[1] = f2pack(a0.z, a0.w);
        ap[2] = f2pack(a1.x, a1.y); ap[3] = f2pack(a1.z, a1.w);
        unsigned long long bb[6];
        bb[0] = f2pack(b0.x, b0.x); bb[1] = f2pack(b0.y, b0.y);
        bb[2] = f2pack(b1.x, b1.x); bb[3] = f2pack(b1.y, b1.y);
        bb[4] = f2pack(b2.x, b2.x); bb[5] = f2pack(b2.y, b2.y);
#pragma unroll
        for (int i = 0; i < 4; i++)
#pragma unroll
            for (int j = 0; j < 6; j++) f2fma(acc2[i][j], ap[i], bb[j]);
    }
#pragma unroll
    for (int i = 0; i < 4; i++)
#pragma unroll
        for (int j = 0; j < 6; j++) f2unpack(acc[2 * i][j], acc[2 * i + 1][j], acc2[i][j]);
}

// ---------------- kernel 2: QKV GEMM ----------------
__global__ __launch_bounds__(256, 2) void qkv_gemm(const float* __restrict__ x,
                                                   const float* __restrict__ W,
                                                   const float* __restrict__ bias) {
    extern __shared__ float sm[];
    float* xs_t = sm;
    float* ws_t = sm + 96 * 132;
    const int tid   = threadIdx.x;
    const int which = blockIdx.y;
    const int m0    = blockIdx.x * 128;

    float acc[8][6];
    gemm_core(x + (size_t)m0 * 96, W + (size_t)which * 96 * 96, xs_t, ws_t, acc, tid);

    const int tx = tid & 15, ty = tid >> 4;
    float* base = (which == 0) ? g_q : (which == 1) ? g_k : g_v;
#pragma unroll
    for (int i = 0; i < 8; i++) {
        int m = m0 + ty * 8 + i;
        int bw = m / N_, n = m - bw * N_;
#pragma unroll
        for (int j = 0; j < 6; j++) {
            int c = tx * 6 + j;
            int h = c >> 5, d = c & 31;
            base[(((size_t)bw * HEADS + h) * N_ + n) * HD + d] = acc[i][j] + bias[which * 96 + c];
        }
    }
}

// ---------------- cp.async helpers ----------------
__device__ __forceinline__ void cp_async16(float* smem_dst, const float* gmem_src) {
    unsigned saddr = (unsigned)__cvta_generic_to_shared(smem_dst);
    asm volatile("cp.async.cg.shared.global [%0], [%1], 16;\n" :: "r"(saddr), "l"(gmem_src));
}
__device__ __forceinline__ void cp_async_commit() {
    asm volatile("cp.async.commit_group;\n" ::: "memory");
}
__device__ __forceinline__ void cp_async_wait0() {
    asm volatile("cp.async.wait_group 0;\n" ::: "memory");
}

// prefetch bm rows for tile i0 into warp-owned ps rows (base ty*4). 86 float4/row.
template<int RPW>
__device__ __forceinline__ void prefetch_bm(int i0, float* ps,
                                            const float* __restrict__ bmb,
                                            int ty, int tx) {
#pragma unroll
    for (int rr = 0; rr < RPW; rr++) {
        int i = i0 + ty * RPW + rr;
        if (i > N_ - 1) i = N_ - 1;                 // clamped rows (discarded later)
        const float* src = bmb + (size_t)i * PSW;
        float* dst = ps + (ty * 4 + rr) * PSW;
        cp_async16(dst + tx * 4,        src + tx * 4);
        cp_async16(dst + (tx + 32) * 4, src + (tx + 32) * 4);
        if (tx < 22)
            cp_async16(dst + (tx + 64) * 4, src + (tx + 64) * 4);
    }
    cp_async_commit();
}

// ---------------- attn tile worker (16 warps, RPW rows per warp, f32x2 math) ----------------
// ps row ownership is warp-constant: warp ty ALWAYS uses ps rows [ty*4, ty*4+RPW).
template<int RPW>
__device__ __forceinline__ void attn_tile(int i0, float* sm,
                                          float scl, int b, int h, int ty, int tx) {
    static_assert(RPW % 2 == 0, "RPW must be even for f32x2 row pairing");
    constexpr int NP = RPW / 2;
    float* ks = sm + KS_OFF;
    float* vs = sm + VS_OFF;
    float* qs = sm + QS_OFF;
    float* ps = sm + PS_OFF;

    // ---- Phase A: S = Q K^T (row-pairs packed in f32x2) ----
    unsigned long long acc2[NP][11];
#pragma unroll
    for (int p = 0; p < NP; p++)
#pragma unroll
        for (int t = 0; t < 11; t++) acc2[p][t] = 0ull;

#pragma unroll
    for (int d0 = 0; d0 < 32; d0 += 4) {
        unsigned long long qp[NP][4];
#pragma unroll
        for (int p = 0; p < NP; p++) {
            int r0 = i0 + ty * RPW + 2 * p;
            r0 = (r0 < NROWS) ? r0 : 0;
            int r1 = i0 + ty * RPW + 2 * p + 1;
            r1 = (r1 < NROWS) ? r1 : 0;
            float4 qa = *(const float4*)&qs[r0 * 36 + d0];   // broadcast
            float4 qb = *(const float4*)&qs[r1 * 36 + d0];
            qp[p][0] = f2pack(qa.x, qb.x); qp[p][1] = f2pack(qa.y, qb.y);
            qp[p][2] = f2pack(qa.z, qb.z); qp[p][3] = f2pack(qa.w, qb.w);
        }
#pragma unroll
        for (int t = 0; t < 11; t++) {
            int j = tx + 32 * t;                     // j>=NROWS reads in-bounds junk; masked later
            float4 k4 = *(const float4*)&ks[j * 36 + d0];
            unsigned long long kk0 = f2pack(k4.x, k4.x);
            unsigned long long kk1 = f2pack(k4.y, k4.y);
            unsigned long long kk2 = f2pack(k4.z, k4.z);
            unsigned long long kk3 = f2pack(k4.w, k4.w);
#pragma unroll
            for (int p = 0; p < NP; p++) {
                f2fma(acc2[p][t], qp[p][0], kk0);
                f2fma(acc2[p][t], qp[p][1], kk1);
                f2fma(acc2[p][t], qp[p][2], kk2);
                f2fma(acc2[p][t], qp[p][3], kk3);
            }
        }
    }

    float acc[RPW][11];
#pragma unroll
    for (int p = 0; p < NP; p++)
#pragma unroll
        for (int t = 0; t < 11; t++)
            f2unpack(acc[2 * p][t], acc[2 * p + 1][t], acc2[p][t]);

    // ---- wait for this tile's bm prefetch, then softmax (warp-local rows) ----
    cp_async_wait0();
    __syncwarp();
#pragma unroll
    for (int rr = 0; rr < RPW; rr++) {
        const float* bmrow = ps + (ty * 4 + rr) * PSW;
        float mx = -1e30f;
#pragma unroll
        for (int t = 0; t < 11; t++) {
            int j = tx + 32 * t;
            float s = (j < N_) ? fmaf(acc[rr][t], scl, bmrow[j]) : -1e30f;
            acc[rr][t] = s;
            mx = fmaxf(mx, s);
        }
#pragma unroll
        for (int o = 16; o; o >>= 1) mx = fmaxf(mx, __shfl_xor_sync(0xffffffffu, mx, o));
        float sum = 0.0f;
#pragma unroll
        for (int t = 0; t < 11; t++) {
            int j = tx + 32 * t;
            float e = (j < N_) ? __expf(acc[rr][t] - mx) : 0.0f;
            acc[rr][t] = e;
            sum += e;
        }
#pragma unroll
        for (int o = 16; o; o >>= 1) sum += __shfl_xor_sync(0xffffffffu, sum, o);
        float inv = 1.0f / sum;
#pragma unroll
        for (int t = 0; t < 11; t++) {
            int j = tx + 32 * t;
            if (j < PSW)
                ps[(ty * 4 + rr) * PSW + j] = acc[rr][t] * inv;   // overwrite bm with p
        }
    }
    __syncwarp();

    // ---- Phase B: O = P V (row-pairs packed in f32x2, lane = output dim) ----
    unsigned long long o2[NP];
#pragma unroll
    for (int p = 0; p < NP; p++) o2[p] = 0ull;

#pragma unroll 2
    for (int j0 = 0; j0 < PSW; j0 += 4) {
        unsigned long long pp[NP][4];
#pragma unroll
        for (int p = 0; p < NP; p++) {
            float4 pa = *(const float4*)&ps[(ty * 4 + 2 * p) * PSW + j0];      // broadcast
            float4 pb = *(const float4*)&ps[(ty * 4 + 2 * p + 1) * PSW + j0];
            pp[p][0] = f2pack(pa.x, pb.x); pp[p][1] = f2pack(pa.y, pb.y);
            pp[p][2] = f2pack(pa.z, pb.z); pp[p][3] = f2pack(pa.w, pb.w);
        }
#pragma unroll
        for (int jj = 0; jj < 4; jj++) {
            float vv = vs[(j0 + jj) * 32 + tx];
            unsigned long long vv2 = f2pack(vv, vv);
#pragma unroll
            for (int p = 0; p < NP; p++)
                f2fma(o2[p], pp[p][jj], vv2);
        }
    }
#pragma unroll
    for (int p = 0; p < NP; p++) {
        float o0, o1;
        f2unpack(o0, o1, o2[p]);
        int i = i0 + ty * RPW + 2 * p;
        if (i < N_)
            g_ao[((size_t)b * N_ + i) * DIM_ + h * HD + tx] = o0;
        if (i + 1 < N_)
            g_ao[((size_t)b * N_ + i + 1) * DIM_ + h * HD + tx] = o1;
    }
    __syncwarp();
}

// ---------------- kernel 3: attention (512 threads = 16 warps = 4/SMSP) ----------------
// smem: ks [344][36], vs [344][32], qs [344][36], ps [64][344] = 231168 B
__global__ __launch_bounds__(512) void attn_kernel(const float* __restrict__ logit_scale) {
    extern __shared__ float sm[];
    float* ks = sm + KS_OFF;
    float* vs = sm + VS_OFF;
    float* qs = sm + QS_OFF;
    float* ps = sm + PS_OFF;

    const int bx = blockIdx.x;
    const int b  = bx / HEADS;
    const int h  = bx - b * HEADS;
    const int w  = b & (NW_ - 1);
    const int tid = threadIdx.x;
    const int ty = tid >> 5, tx = tid & 31;   // ty: 0..15

    const size_t bh = (size_t)b * HEADS + h;
    const float* qg = g_q + bh * N_ * HD;
    const float* kg = g_k + bh * N_ * HD;
    const float* vg = g_v + bh * N_ * HD;

    const float* bmb = g_bm + ((size_t)w * HEADS + h) * N_ * PSW;

    // tile-0 bm prefetch overlaps staging (ps untouched by staging; warp-private rows)
    prefetch_bm<4>(0, ps, bmb, ty, tx);

    // stage rows 0..343 (row 343 zero-filled), fused q/k L2 normalization
    for (int r = ty; r < NROWS; r += 16) {
        float qv = 0.f, kv = 0.f, vv = 0.f;
        if (r < N_) {
            int off = r * HD + tx;
            qv = qg[off]; kv = kg[off]; vv = vg[off];
        }
        float qss = qv * qv, kss = kv * kv;
#pragma unroll
        for (int o = 16; o; o >>= 1) {
            qss += __shfl_xor_sync(0xffffffffu, qss, o);
            kss += __shfl_xor_sync(0xffffffffu, kss, o);
        }
        float qinv = 1.0f / fmaxf(sqrtf(qss), 1e-12f);
        float kinv = 1.0f / fmaxf(sqrtf(kss), 1e-12f);
        qs[r * 36 + tx] = qv * qinv;
        ks[r * 36 + tx] = kv * kinv;
        vs[r * 32 + tx] = vv;
    }
    __syncthreads();

    const float scl = fminf(__expf(logit_scale[h]), 100.0f);

    // pipeline: prefetch(t) ... PhaseA(t) | wait | softmax(t) PhaseB(t) prefetch(t+1)
#pragma unroll 1
    for (int i0 = 0; i0 < 320; i0 += 64) {
        attn_tile<4>(i0, sm, scl, b, h, ty, tx);
        if (i0 + 64 < 320) prefetch_bm<4>(i0 + 64, ps, bmb, ty, tx);
        else               prefetch_bm<2>(320,     ps, bmb, ty, tx);
    }
    attn_tile<2>(320, sm, scl, b, h, ty, tx);   // rows 320..351 (tail)
}

// ---------------- kernel 4: output projection ----------------
__global__ __launch_bounds__(256, 2) void proj_gemm(const float* __restrict__ W,
                                                    const float* __restrict__ bias,
                                                    float* __restrict__ out) {
    extern __shared__ float sm[];
    float* xs_t = sm;
    float* ws_t = sm + 96 * 132;
    const int tid = threadIdx.x;
    const int m0  = blockIdx.x * 128;

    float acc[8][6];
    gemm_core(g_ao + (size_t)m0 * 96, W, xs_t, ws_t, acc, tid);

    const int tx = tid & 15, ty = tid >> 4;
#pragma unroll
    for (int i = 0; i < 8; i++) {
        int m = m0 + ty * 8 + i;
#pragma unroll
        for (int j = 0; j < 6; j++) {
            int c = tx * 6 + j;
            out[(size_t)m * 96 + c] = acc[i][j] + bias[c];
        }
    }
}

// ---------------- launch ----------------
extern "C" void kernel_launch(void* const* d_in, const int* in_sizes, int n_in,
                              void* d_out, int out_size) {
    const float* x     = (const float*)d_in[0];
    const float* mask  = (const float*)d_in[1];
    const float* Wqkv  = (const float*)d_in[2];
    const float* bqkv  = (const float*)d_in[3];
    const float* Wproj = (const float*)d_in[4];
    const float* bproj = (const float*)d_in[5];
    const float* ls    = (const float*)d_in[6];
    const float* table = (const float*)d_in[7];
    const int*   rpi   = (const int*)d_in[8];
    float* out = (float*)d_out;

    const int smG = (96 * 132 + 96 * 100) * 4;   // 89088 B
    const int smA = SM_FLOATS * 4;               // 231168 B
    cudaFuncSetAttribute(qkv_gemm,  cudaFuncAttributeMaxDynamicSharedMemorySize, smG);
    cudaFuncSetAttribute(proj_gemm, cudaFuncAttributeMaxDynamicSharedMemorySize, smG);
    cudaFuncSetAttribute(attn_kernel, cudaFuncAttributeMaxDynamicSharedMemorySize, smA);

    const size_t bm_total = (size_t)NW_ * HEADS * N_ * PSW;
    bm_kernel<<<(unsigned)((bm_total + 255) / 256), 256>>>(rpi, table, mask);
    qkv_gemm<<<dim3(ROWS_TOT / 128, 3), 256, smG>>>(x, Wqkv, bqkv);
    attn_kernel<<<BW_ * HEADS, 512, smA>>>(ls);
    proj_gemm<<<ROWS_TOT / 128, 256, smG>>>(Wproj, bproj, out);
}

// round 15
// speedup vs baseline: 1.2325x; 1.0898x over previous
#include <cuda_runtime.h>
#include <math.h>

// ---------------- problem constants ----------------
#define BW_   512              // total windows
#define NW_   64               // mask batch
#define N_    343              // tokens per window
#define NROWS 344              // smem rows actually stored
#define PSW   344              // ps / bm row stride (mult of 4)
#define DIM_  96
#define HEADS 3
#define HD    32
#define NN_   (N_ * N_)        // 117649
#define ROWS_TOT (BW_ * N_)    // 175616

// smem float offsets for attn (ks stride 36, vs stride 32, qs stride 36, ps 64x344)
#define KS_OFF 0
#define VS_OFF (NROWS * 36)
#define QS_OFF (NROWS * 36 + NROWS * 32)
#define PS_OFF (2 * NROWS * 36 + NROWS * 32)
#define SM_FLOATS (PS_OFF + 64 * PSW)      // 57792 floats = 231168 B

// ---------------- f32x2 packed helpers (sm_103a) — used in GEMMs only ----------------
__device__ __forceinline__ unsigned long long f2pack(float lo, float hi) {
    unsigned long long r;
    asm("mov.b64 %0, {%1, %2};" : "=l"(r) : "f"(lo), "f"(hi));
    return r;
}
__device__ __forceinline__ void f2unpack(float& lo, float& hi, unsigned long long v) {
    asm("mov.b64 {%0, %1}, %2;" : "=f"(lo), "=f"(hi) : "l"(v));
}
__device__ __forceinline__ void f2fma(unsigned long long& d, unsigned long long a,
                                      unsigned long long b) {
    asm("fma.rn.f32x2 %0, %1, %2, %3;" : "=l"(d) : "l"(a), "l"(b), "l"(d));
}

// ---------------- device scratch ----------------
__device__ float g_q [BW_ * HEADS * N_ * HD];
__device__ float g_k [BW_ * HEADS * N_ * HD];
__device__ float g_v [BW_ * HEADS * N_ * HD];
__device__ float g_ao[ROWS_TOT * DIM_];
__device__ float g_bm[(size_t)NW_ * HEADS * N_ * PSW];   // bias+mask, padded rows

// ---------------- kernel 1: combined bias+mask table ----------------
__global__ void bm_kernel(const int* __restrict__ rpi, const float* __restrict__ table,
                          const float* __restrict__ mask) {
    size_t idx = (size_t)blockIdx.x * blockDim.x + threadIdx.x;
    const size_t total = (size_t)NW_ * HEADS * N_ * PSW;
    if (idx >= total) return;
    int j  = (int)(idx % PSW);
    size_t rest = idx / PSW;
    int i  = (int)(rest % N_);
    int wh = (int)(rest / N_);
    int h  = wh % HEADS;
    int w  = wh / HEADS;
    float v = 0.0f;
    if (j < N_)
        v = table[rpi[i * N_ + j] * HEADS + h] + mask[((size_t)w * N_ + i) * N_ + j];
    g_bm[idx] = v;
}

// ---------------- GEMM core (k-major smem, packed f32x2 inner loop) ----------------
__device__ __forceinline__ void gemm_core(const float* __restrict__ xg4,   // 128x96 tile
                                          const float* __restrict__ wg4,   // 96x96 slice
                                          float* xs_t, float* ws_t,
                                          float acc[8][6], int tid) {
    {
        const float4* xg = (const float4*)xg4;
        for (int i = tid; i < 128 * 24; i += 256) {
            int r = i / 24, c4 = i % 24;
            float4 v = xg[r * 24 + c4];
            xs_t[(c4 * 4 + 0) * 132 + r] = v.x;
            xs_t[(c4 * 4 + 1) * 132 + r] = v.y;
            xs_t[(c4 * 4 + 2) * 132 + r] = v.z;
            xs_t[(c4 * 4 + 3) * 132 + r] = v.w;
        }
    }
    {
        const float4* wg = (const float4*)wg4;
        for (int i = tid; i < 96 * 24; i += 256) {
            int r = i / 24, c4 = i % 24;
            float4 v = wg[r * 24 + c4];
            ws_t[(c4 * 4 + 0) * 100 + r] = v.x;
            ws_t[(c4 * 4 + 1) * 100 + r] = v.y;
            ws_t[(c4 * 4 + 2) * 100 + r] = v.z;
            ws_t[(c4 * 4 + 3) * 100 + r] = v.w;
        }
    }
    __syncthreads();

    const int tx = tid & 15, ty = tid >> 4;
    unsigned long long acc2[4][6];
#pragma unroll
    for (int i = 0; i < 4; i++)
#pragma unroll
        for (int j = 0; j < 6; j++) acc2[i][j] = 0ull;

#pragma unroll 4
    for (int k = 0; k < 96; k++) {
        float4 a0 = *(const float4*)&xs_t[k * 132 + ty * 8];
        float4 a1 = *(const float4*)&xs_t[k * 132 + ty * 8 + 4];
        float2 b0 = *(const float2*)&ws_t[k * 100 + tx * 6];
        float2 b1 = *(const float2*)&ws_t[k * 100 + tx * 6 + 2];
        float2 b2 = *(const float2*)&ws_t[k * 100 + tx * 6 + 4];
        unsigned long long ap[4];
        ap[0] = f2pack(a0.x, a0.y); ap[1] = f2pack(a0.z, a0.w);
        ap[2] = f2pack(a1.x, a1.y); ap[3] = f2pack(a1.z, a1.w);
        unsigned long long bb[6];
        bb[0] = f2pack(b0.x, b0.x); bb[1] = f2pack(b0.y, b0.y);
        bb[2] = f2pack(b1.x, b1.x); bb[3] = f2pack(b1.y, b1.y);
        bb[4] = f2pack(b2.x, b2.x); bb[5] = f2pack(b2.y, b2.y);
#pragma unroll
        for (int i = 0; i < 4; i++)
#pragma unroll
            for (int j = 0; j < 6; j++) f2fma(acc2[i][j], ap[i], bb[j]);
    }
#pragma unroll
    for (int i = 0; i < 4; i++)
#pragma unroll
        for (int j = 0; j < 6; j++) f2unpack(acc[2 * i][j], acc[2 * i + 1][j], acc2[i][j]);
}

// ---------------- kernel 2: QKV GEMM ----------------
__global__ __launch_bounds__(256, 2) void qkv_gemm(const float* __restrict__ x,
                                                   const float* __restrict__ W,
                                                   const float* __restrict__ bias) {
    extern __shared__ float sm[];
    float* xs_t = sm;
    float* ws_t = sm + 96 * 132;
    const int tid   = threadIdx.x;
    const int which = blockIdx.y;
    const int m0    = blockIdx.x * 128;

    float acc[8][6];
    gemm_core(x + (size_t)m0 * 96, W + (size_t)which * 96 * 96, xs_t, ws_t, acc, tid);

    const int tx = tid & 15, ty = tid >> 4;
    float* base = (which == 0) ? g_q : (which == 1) ? g_k : g_v;
#pragma unroll
    for (int i = 0; i < 8; i++) {
        int m = m0 + ty * 8 + i;
        int bw = m / N_, n = m - bw * N_;
#pragma unroll
        for (int j = 0; j < 6; j++) {
            int c = tx * 6 + j;
            int h = c >> 5, d = c & 31;
            base[(((size_t)bw * HEADS + h) * N_ + n) * HD + d] = acc[i][j] + bias[which * 96 + c];
        }
    }
}

// ---------------- cp.async helpers ----------------
__device__ __forceinline__ void cp_async16(float* smem_dst, const float* gmem_src) {
    unsigned saddr = (unsigned)__cvta_generic_to_shared(smem_dst);
    asm volatile("cp.async.cg.shared.global [%0], [%1], 16;\n" :: "r"(saddr), "l"(gmem_src));
}
__device__ __forceinline__ void cp_async_commit() {
    asm volatile("cp.async.commit_group;\n" ::: "memory");
}
__device__ __forceinline__ void cp_async_wait0() {
    asm volatile("cp.async.wait_group 0;\n" ::: "memory");
}

// prefetch bm rows for tile i0 into warp-owned ps rows (base ty*4). 86 float4/row.
template<int RPW>
__device__ __forceinline__ void prefetch_bm(int i0, float* ps,
                                            const float* __restrict__ bmb,
                                            int ty, int tx) {
#pragma unroll
    for (int rr = 0; rr < RPW; rr++) {
        int i = i0 + ty * RPW + rr;
        if (i > N_ - 1) i = N_ - 1;                 // clamped rows (discarded later)
        const float* src = bmb + (size_t)i * PSW;
        float* dst = ps + (ty * 4 + rr) * PSW;
        cp_async16(dst + tx * 4,        src + tx * 4);
        cp_async16(dst + (tx + 32) * 4, src + (tx + 32) * 4);
        if (tx < 22)
            cp_async16(dst + (tx + 64) * 4, src + (tx + 64) * 4);
    }
    cp_async_commit();
}

// ---------------- attn tile worker (16 warps, RPW rows per warp, scalar math) ----------------
// ps row ownership is warp-constant: warp ty ALWAYS uses ps rows [ty*4, ty*4+RPW).
// Softmax reductions interleave the RPW rows' shuffle chains (same per-row op order
// as before -> bit-identical results, ~RPW× less exposed SHFL latency).
template<int RPW>
__device__ __forceinline__ void attn_tile(int i0, float* sm,
                                          float scl, int b, int h, int ty, int tx) {
    float* ks = sm + KS_OFF;
    float* vs = sm + VS_OFF;
    float* qs = sm + QS_OFF;
    float* ps = sm + PS_OFF;

    // ---- Phase A: S = Q K^T ----
    float acc[RPW][11];
#pragma unroll
    for (int rr = 0; rr < RPW; rr++)
#pragma unroll
        for (int t = 0; t < 11; t++) acc[rr][t] = 0.0f;

#pragma unroll
    for (int d0 = 0; d0 < 32; d0 += 4) {
        float qa[RPW][4];
#pragma unroll
        for (int rr = 0; rr < RPW; rr++) {
            int row = i0 + ty * RPW + rr;
            row = (row < NROWS) ? row : 0;          // qs has NROWS rows
            float4 q4 = *(const float4*)&qs[row * 36 + d0];   // broadcast
            qa[rr][0] = q4.x; qa[rr][1] = q4.y; qa[rr][2] = q4.z; qa[rr][3] = q4.w;
        }
#pragma unroll
        for (int t = 0; t < 11; t++) {
            int j = tx + 32 * t;                     // j>=NROWS reads in-bounds junk; masked later
            float4 k4 = *(const float4*)&ks[j * 36 + d0];
#pragma unroll
            for (int rr = 0; rr < RPW; rr++) {
                acc[rr][t] = fmaf(qa[rr][0], k4.x, acc[rr][t]);
                acc[rr][t] = fmaf(qa[rr][1], k4.y, acc[rr][t]);
                acc[rr][t] = fmaf(qa[rr][2], k4.z, acc[rr][t]);
                acc[rr][t] = fmaf(qa[rr][3], k4.w, acc[rr][t]);
            }
        }
    }

    // ---- wait for this tile's bm prefetch, then softmax (warp-local rows) ----
    cp_async_wait0();
    __syncwarp();

    float mx[RPW], sum[RPW];
    // pass 1: add bias+mask, per-lane max
#pragma unroll
    for (int rr = 0; rr < RPW; rr++) {
        const float* bmrow = ps + (ty * 4 + rr) * PSW;
        mx[rr] = -1e30f;
#pragma unroll
        for (int t = 0; t < 11; t++) {
            int j = tx + 32 * t;
            float s = (j < N_) ? fmaf(acc[rr][t], scl, bmrow[j]) : -1e30f;
            acc[rr][t] = s;
            mx[rr] = fmaxf(mx[rr], s);
        }
    }
    // interleaved max reduction (RPW independent shuffle chains)
#pragma unroll
    for (int o = 16; o; o >>= 1)
#pragma unroll
        for (int rr = 0; rr < RPW; rr++)
            mx[rr] = fmaxf(mx[rr], __shfl_xor_sync(0xffffffffu, mx[rr], o));
    // pass 2: exp + per-lane sum
#pragma unroll
    for (int rr = 0; rr < RPW; rr++) {
        sum[rr] = 0.0f;
#pragma unroll
        for (int t = 0; t < 11; t++) {
            int j = tx + 32 * t;
            float e = (j < N_) ? __expf(acc[rr][t] - mx[rr]) : 0.0f;
            acc[rr][t] = e;
            sum[rr] += e;
        }
    }
    // interleaved sum reduction
#pragma unroll
    for (int o = 16; o; o >>= 1)
#pragma unroll
        for (int rr = 0; rr < RPW; rr++)
            sum[rr] += __shfl_xor_sync(0xffffffffu, sum[rr], o);
    // write p
#pragma unroll
    for (int rr = 0; rr < RPW; rr++) {
        float inv = 1.0f / sum[rr];
#pragma unroll
        for (int t = 0; t < 11; t++) {
            int j = tx + 32 * t;
            if (j < PSW)
                ps[(ty * 4 + rr) * PSW + j] = acc[rr][t] * inv;   // overwrite bm with p
        }
    }
    __syncwarp();

    // ---- Phase B: O = P V (lane = output dim) ----
    float o[RPW];
#pragma unroll
    for (int rr = 0; rr < RPW; rr++) o[rr] = 0.0f;

#pragma unroll 2
    for (int j0 = 0; j0 < PSW; j0 += 4) {
        float pa[RPW][4];
#pragma unroll
        for (int rr = 0; rr < RPW; rr++) {
            float4 p4 = *(const float4*)&ps[(ty * 4 + rr) * PSW + j0];  // broadcast
            pa[rr][0] = p4.x; pa[rr][1] = p4.y; pa[rr][2] = p4.z; pa[rr][3] = p4.w;
        }
#pragma unroll
        for (int jj = 0; jj < 4; jj++) {
            float vv = vs[(j0 + jj) * 32 + tx];
#pragma unroll
            for (int rr = 0; rr < RPW; rr++)
                o[rr] = fmaf(pa[rr][jj], vv, o[rr]);
        }
    }
#pragma unroll
    for (int rr = 0; rr < RPW; rr++) {
        int i = i0 + ty * RPW + rr;
        if (i < N_)
            g_ao[((size_t)b * N_ + i) * DIM_ + h * HD + tx] = o[rr];
    }
    __syncwarp();
}

// ---------------- kernel 3: attention (512 threads = 16 warps = 4/SMSP) ----------------
// smem: ks [344][36], vs [344][32], qs [344][36], ps [64][344] = 231168 B
__global__ __launch_bounds__(512) void attn_kernel(const float* __restrict__ logit_scale) {
    extern __shared__ float sm[];
    float* ks = sm + KS_OFF;
    float* vs = sm + VS_OFF;
    float* qs = sm + QS_OFF;
    float* ps = sm + PS_OFF;

    const int bx = blockIdx.x;
    const int b  = bx / HEADS;
    const int h  = bx - b * HEADS;
    const int w  = b & (NW_ - 1);
    const int tid = threadIdx.x;
    const int ty = tid >> 5, tx = tid & 31;   // ty: 0..15

    const size_t bh = (size_t)b * HEADS + h;
    const float* qg = g_q + bh * N_ * HD;
    const float* kg = g_k + bh * N_ * HD;
    const float* vg = g_v + bh * N_ * HD;

    const float* bmb = g_bm + ((size_t)w * HEADS + h) * N_ * PSW;

    // tile-0 bm prefetch overlaps staging (ps untouched by staging; warp-private rows)
    prefetch_bm<4>(0, ps, bmb, ty, tx);

    // stage rows 0..343 (row 343 zero-filled), fused q/k L2 normalization
    for (int r = ty; r < NROWS; r += 16) {
        float qv = 0.f, kv = 0.f, vv = 0.f;
        if (r < N_) {
            int off = r * HD + tx;
            qv = qg[off]; kv = kg[off]; vv = vg[off];
        }
        float qss = qv * qv, kss = kv * kv;
#pragma unroll
        for (int o = 16; o; o >>= 1) {
            qss += __shfl_xor_sync(0xffffffffu, qss, o);
            kss += __shfl_xor_sync(0xffffffffu, kss, o);
        }
        float qinv = 1.0f / fmaxf(sqrtf(qss), 1e-12f);
        float kinv = 1.0f / fmaxf(sqrtf(kss), 1e-12f);
        qs[r * 36 + tx] = qv * qinv;
        ks[r * 36 + tx] = kv * kinv;
        vs[r * 32 + tx] = vv;
    }
    __syncthreads();

    const float scl = fminf(__expf(logit_scale[h]), 100.0f);

    // pipeline: prefetch(t) ... PhaseA(t) | wait | softmax(t) PhaseB(t) prefetch(t+1)
#pragma unroll 1
    for (int i0 = 0; i0 < 320; i0 += 64) {
        attn_tile<4>(i0, sm, scl, b, h, ty, tx);
        if (i0 + 64 < 320) prefetch_bm<4>(i0 + 64, ps, bmb, ty, tx);
        else               prefetch_bm<2>(320,     ps, bmb, ty, tx);
    }
    attn_tile<2>(320, sm, scl, b, h, ty, tx);   // rows 320..351 (tail)
}

// ---------------- kernel 4: output projection ----------------
__global__ __launch_bounds__(256, 2) void proj_gemm(const float* __restrict__ W,
                                                    const float* __restrict__ bias,
                                                    float* __restrict__ out) {
    extern __shared__ float sm[];
    float* xs_t = sm;
    float* ws_t = sm + 96 * 132;
    const int tid = threadIdx.x;
    const int m0  = blockIdx.x * 128;

    float acc[8][6];
    gemm_core(g_ao + (size_t)m0 * 96, W, xs_t, ws_t, acc, tid);

    const int tx = tid & 15, ty = tid >> 4;
#pragma unroll
    for (int i = 0; i < 8; i++) {
        int m = m0 + ty * 8 + i;
#pragma unroll
        for (int j = 0; j < 6; j++) {
            int c = tx * 6 + j;
            out[(size_t)m * 96 + c] = acc[i][j] + bias[c];
        }
    }
}

// ---------------- launch ----------------
extern "C" void kernel_launch(void* const* d_in, const int* in_sizes, int n_in,
                              void* d_out, int out_size) {
    const float* x     = (const float*)d_in[0];
    const float* mask  = (const float*)d_in[1];
    const float* Wqkv  = (const float*)d_in[2];
    const float* bqkv  = (const float*)d_in[3];
    const float* Wproj = (const float*)d_in[4];
    const float* bproj = (const float*)d_in[5];
    const float* ls    = (const float*)d_in[6];
    const float* table = (const float*)d_in[7];
    const int*   rpi   = (const int*)d_in[8];
    float* out = (float*)d_out;

    const int smG = (96 * 132 + 96 * 100) * 4;   // 89088 B
    const int smA = SM_FLOATS * 4;               // 231168 B
    cudaFuncSetAttribute(qkv_gemm,  cudaFuncAttributeMaxDynamicSharedMemorySize, smG);
    cudaFuncSetAttribute(proj_gemm, cudaFuncAttributeMaxDynamicSharedMemorySize, smG);
    cudaFuncSetAttribute(attn_kernel, cudaFuncAttributeMaxDynamicSharedMemorySize, smA);

    const size_t bm_total = (size_t)NW_ * HEADS * N_ * PSW;
    bm_kernel<<<(unsigned)((bm_total + 255) / 256), 256>>>(rpi, table, mask);
    qkv_gemm<<<dim3(ROWS_TOT / 128, 3), 256, smG>>>(x, Wqkv, bqkv);
    attn_kernel<<<BW_ * HEADS, 512, smA>>>(ls);
    proj_gemm<<<ROWS_TOT / 128, 256, smG>>>(Wproj, bproj, out);
}